// round 15
// baseline (speedup 1.0000x reference)
#include <cuda_runtime.h>
#include <cuda_fp16.h>
#include <cstdint>

// ---------------- problem dims ----------------
#define T_DIM 8192
#define D_DIM 1024
#define H_DIM 4096

// scratch (device globals: no allocation allowed)
__device__ __half g_h  [(size_t)T_DIM * H_DIM];   // 64 MB intermediate (fp16)
__device__ __half g_xh [(size_t)T_DIM * D_DIM];   // fp16 x
__device__ __half g_wfc[(size_t)H_DIM * D_DIM];   // fp16 W_fc
__device__ __half g_wpr[(size_t)D_DIM * H_DIM];   // fp16 W_proj
// sync counters: [0,128) x bands; [128,160) wfc bands; [160,168) wpr bands; [168,296) h bands
__device__ int    g_sync[296];

// ---------------- helpers ----------------
__device__ __forceinline__ uint32_t smem_u32(const void* p) {
    uint32_t a;
    asm("{ .reg .u64 t; cvta.to.shared.u64 t, %1; cvt.u32.u64 %0, t; }" : "=r"(a) : "l"(p));
    return a;
}
__device__ __forceinline__ uint32_t swz(uint32_t b) {   // SW128: XOR bits[6:4] with bits[9:7]
    return b ^ ((b >> 3) & 0x70u);
}
__device__ __forceinline__ void cp_async16(uint32_t saddr, const void* g) {
    asm volatile("cp.async.cg.shared.global [%0], [%1], 16;" :: "r"(saddr), "l"(g));
}
#define CP_COMMIT() asm volatile("cp.async.commit_group;" ::: "memory")
#define CP_WAIT1()  asm volatile("cp.async.wait_group 1;" ::: "memory")

#define LDSM_X4(r0, r1, r2, r3, addr) \
    asm volatile("ldmatrix.sync.aligned.m8n8.x4.shared.b16 {%0,%1,%2,%3}, [%4];" \
        : "=r"(r0), "=r"(r1), "=r"(r2), "=r"(r3) : "r"(addr))

// fp16 MMA, fp32 accumulate: D(16x8) += A(16x16) * B(16x8)
#define MMA_F16(c0, c1, c2, c3, a0, a1, a2, a3, b0, b1) \
    asm volatile("mma.sync.aligned.m16n8k16.row.col.f32.f16.f16.f32 " \
        "{%0,%1,%2,%3}, {%4,%5,%6,%7}, {%8,%9}, {%0,%1,%2,%3};" \
        : "+f"(c0), "+f"(c1), "+f"(c2), "+f"(c3) \
        : "r"(a0), "r"(a1), "r"(a2), "r"(a3), "r"(b0), "r"(b1))

// ---------------- GEMM config ----------------
static constexpr int BLK_N = 128;
static constexpr int BLK_K = 64;                 // fp16 elems -> 128 bytes per row
static constexpr int STAGES = 3;                 // <=96KB -> 2 CTAs / SM
static constexpr int B_BYTES = BLK_N * BLK_K * 2;          // 16384
static constexpr int SMEM_TOTAL = STAGES * (128 * 128 + B_BYTES);   // 98304 (TM=128 worst case)

// fused grid layout
static constexpr int CV_X0   = 0;      // 128 blocks: x bands (64 rows, 16384 float4 each)
static constexpr int CV_WF0  = 128;    // 256 blocks: wfc, 8 per 128-row band (4096 f4 each)
static constexpr int CV_WP0  = 384;    // 256 blocks: wpr, 32 per 128-row band (4096 f4 each)
static constexpr int G1_BASE = 640;
static constexpr int G1_BIG_TILES = 1760;        // rows 0-7039, 55x32
static constexpr int G1_SMALL_ROW0 = 7040;
static constexpr int G1_TOTAL = 2336;
static constexpr int G2_BASE = G1_BASE + G1_TOTAL;   // 2976
static constexpr int G2_BIG_TILES = 296;         // rows 0-4735
static constexpr int G2_SMALL_ROW0 = 4736;
static constexpr int G2_TOTAL = 728;
static constexpr int GRID_TOTAL = G2_BASE + G2_TOTAL; // 3704

// counter index bases
static constexpr int SC_X = 0, SC_WF = 128, SC_WP = 160, SC_H = 168;

// load one TMx64 A tile + 128x64 B tile (fp16) into stage at sBase
template <int TM>
__device__ __forceinline__ void load_tile_t(uint32_t sBase, const __half* __restrict__ gA,
                                            const __half* __restrict__ gB, int K, int kt, int tid)
{
    const int k0 = kt * BLK_K;
    constexpr int A_BY = TM * 128;
    #pragma unroll
    for (int i = 0; i < TM * 8 / 256; ++i) {       // A: TM*8 x 16B chunks / 256 thr
        int chunk = tid + i * 256;
        int row = chunk >> 3, unit = chunk & 7;    // 8 x 16B units per 128B row
        uint32_t off = row * 128 + unit * 16;
        cp_async16(sBase + swz(off), gA + (size_t)row * K + k0 + unit * 8);
    }
    #pragma unroll
    for (int i = 0; i < 4; ++i) {                  // B
        int chunk = tid + i * 256;
        int row = chunk >> 3, unit = chunk & 7;
        uint32_t off = row * 128 + unit * 16;
        cp_async16(sBase + A_BY + swz(off), gB + (size_t)row * K + k0 + unit * 8);
    }
}

// common mainloop body
template <bool RELU2, bool OUT16, int TM, int WGM>
__device__ __forceinline__ void gemm_body(
    const __half* __restrict__ A, const __half* __restrict__ B, void* __restrict__ Cv,
    int K, int ldc, int m0, int n0)
{
    extern __shared__ char smem[];
    constexpr int MI = TM / (16 * WGM);
    constexpr int NJ = WGM;
    constexpr int A_BY = TM * 128;
    constexpr int STG = A_BY + B_BYTES;
    const uint32_t sb = smem_u32(smem);
    const int tid  = threadIdx.x;
    const int lane = tid & 31;
    const int warp = tid >> 5;
    const int wm = (warp % WGM) * (TM / WGM);
    const int wn = (warp / WGM) * (16 * WGM);

    const __half* gA = A + (size_t)m0 * K;
    const __half* gB = B + (size_t)n0 * K;
    const int KT = K / BLK_K;

    // prologue: 2 stages in flight
    load_tile_t<TM>(sb, gA, gB, K, 0, tid);
    CP_COMMIT();
    load_tile_t<TM>(sb + STG, gA, gB, K, 1, tid);
    CP_COMMIT();

    // ldmatrix linear offsets (swizzle XOR applied per access)
    const uint32_t xmask = (uint32_t)(lane & 7) << 4;
    uint32_t aLin[MI];
    #pragma unroll
    for (int mi = 0; mi < MI; ++mi)
        aLin[mi] = (uint32_t)(wm + mi * 16 + (lane & 15)) * 128 + (uint32_t)(lane >> 4) * 16;
    uint32_t bLin[NJ];
    #pragma unroll
    for (int jp = 0; jp < NJ; ++jp)
        bLin[jp] = (uint32_t)(wn + jp * 16 + (lane & 15)) * 128 + (uint32_t)(lane >> 4) * 16;

    float c[MI][2 * NJ][4];
    #pragma unroll
    for (int mi = 0; mi < MI; ++mi)
        #pragma unroll
        for (int j = 0; j < 2 * NJ; ++j)
            #pragma unroll
            for (int q = 0; q < 4; ++q) c[mi][j][q] = 0.0f;

    int curSt = 0, pfSt = 2;
    for (int kt = 0; kt < KT; ++kt) {
        CP_WAIT1();
        __syncthreads();

        // prefetch k-tile kt+2 into the slot consumed at kt-1
        int nk = kt + 2;
        if (nk < KT) load_tile_t<TM>(sb + pfSt * STG, gA, gB, K, nk, tid);
        CP_COMMIT();
        if (++pfSt == STAGES) pfSt = 0;

        const uint32_t st = sb + curSt * STG;
        if (++curSt == STAGES) curSt = 0;

        #pragma unroll
        for (int s = 0; s < 4; ++s) {              // 4 x K=16 steps (32B each)
            const uint32_t add = s * 32;
            uint32_t a[MI][4], b[NJ][4];
            #pragma unroll
            for (int mi = 0; mi < MI; ++mi)
                LDSM_X4(a[mi][0], a[mi][1], a[mi][2], a[mi][3], st + ((aLin[mi] + add) ^ xmask));
            #pragma unroll
            for (int jp = 0; jp < NJ; ++jp)
                LDSM_X4(b[jp][0], b[jp][1], b[jp][2], b[jp][3],
                        st + A_BY + ((bLin[jp] + add) ^ xmask));
            #pragma unroll
            for (int mi = 0; mi < MI; ++mi)
                #pragma unroll
                for (int jp = 0; jp < NJ; ++jp) {
                    MMA_F16(c[mi][2 * jp][0], c[mi][2 * jp][1], c[mi][2 * jp][2], c[mi][2 * jp][3],
                            a[mi][0], a[mi][1], a[mi][2], a[mi][3], b[jp][0], b[jp][2]);
                    MMA_F16(c[mi][2 * jp + 1][0], c[mi][2 * jp + 1][1], c[mi][2 * jp + 1][2], c[mi][2 * jp + 1][3],
                            a[mi][0], a[mi][1], a[mi][2], a[mi][3], b[jp][1], b[jp][3]);
                }
        }
    }

    // epilogue
    const int row0 = m0 + wm + (lane >> 2);
    const int col0 = n0 + wn + (lane & 3) * 2;
    #pragma unroll
    for (int mi = 0; mi < MI; ++mi)
        #pragma unroll
        for (int rr = 0; rr < 2; ++rr) {
            const int row = row0 + mi * 16 + rr * 8;
            #pragma unroll
            for (int j = 0; j < 2 * NJ; ++j) {
                float v0 = c[mi][j][rr * 2], v1 = c[mi][j][rr * 2 + 1];
                if (RELU2) {
                    v0 = fmaxf(v0, 0.0f); v0 *= v0;
                    v1 = fmaxf(v1, 0.0f); v1 *= v1;
                }
                if (OUT16) {
                    __half* base = (__half*)Cv + (size_t)row * ldc + col0;
                    __half2 hv = __floats2half2_rn(v0, v1);
                    *reinterpret_cast<__half2*>(base + j * 8) = hv;
                } else {
                    float* base = (float*)Cv + (size_t)row * ldc + col0;
                    *reinterpret_cast<float2*>(base + j * 8) = make_float2(v0, v1);
                }
            }
        }
}

// signal: all threads fence+sync, one thread bumps counter(s)
__device__ __forceinline__ void signal_cnt(int idx0, int n)
{
    __threadfence();
    __syncthreads();
    if (threadIdx.x == 0) {
        atomicAdd(&g_sync[idx0], 1);
        if (n == 2) atomicAdd(&g_sync[idx0 + 1], 1);
    }
}

// wait: thread 0 spins until counter reaches target
__device__ __forceinline__ void wait_cnt(int idx, int target)
{
    if (threadIdx.x == 0)
        while (atomicAdd(&g_sync[idx], 0) < target) { __nanosleep(128); }
}
__device__ __forceinline__ void wait_done()
{
    if (threadIdx.x == 0) __threadfence();
    __syncthreads();
}

// convert a contiguous float4 region to __half2 pairs (256 threads)
__device__ __forceinline__ void conv_region(const float4* __restrict__ src,
                                            __half2* __restrict__ dst, int n4)
{
    for (int i = threadIdx.x; i < n4; i += 256) {
        float4 v = src[i];
        dst[2 * i]     = __floats2half2_rn(v.x, v.y);
        dst[2 * i + 1] = __floats2half2_rn(v.z, v.w);
    }
}

// fused: conversion CTAs + GEMM1 tiles + GEMM2 tiles, band-counter dependencies
__global__ void __launch_bounds__(256, 2) fused_all(
    const float4* __restrict__ x, const float4* __restrict__ wf, const float4* __restrict__ wp,
    float* __restrict__ out)
{
    const int bx = blockIdx.x;
    if (bx < CV_WF0) {                       // x conversion: 1 block per 64-row band
        const int band = bx;
        conv_region(x + (size_t)band * 16384, (__half2*)g_xh + (size_t)band * 16384 * 2, 16384);
        signal_cnt(SC_X + band, 1);
    } else if (bx < CV_WP0) {                // wfc conversion: 8 blocks per 128-row band
        const int off = bx - CV_WF0;
        const size_t b4 = (size_t)off * 4096;
        conv_region(wf + b4, (__half2*)g_wfc + b4 * 2, 4096);
        signal_cnt(SC_WF + (off >> 3), 1);
    } else if (bx < G1_BASE) {               // wpr conversion: 32 blocks per 128-row band
        const int off = bx - CV_WP0;
        const size_t b4 = (size_t)off * 4096;
        conv_region(wp + b4, (__half2*)g_wpr + b4 * 2, 4096);
        signal_cnt(SC_WP + (off >> 5), 1);
    } else if (bx < G2_BASE) {               // GEMM1 tiles
        const int t = bx - G1_BASE;
        if (t < G1_BIG_TILES) {
            const int m0 = (t >> 5) * 128, n0 = (t & 31) * 128;
            wait_cnt(SC_X + (m0 >> 6), 1);
            wait_cnt(SC_X + (m0 >> 6) + 1, 1);
            wait_cnt(SC_WF + (n0 >> 7), 8);
            wait_done();
            gemm_body<true, true, 128, 4>(g_xh, g_wfc, g_h, D_DIM, H_DIM, m0, n0);
            signal_cnt(SC_H + (m0 >> 6), 2);
        } else {
            const int i = t - G1_BIG_TILES;
            const int m0 = G1_SMALL_ROW0 + (i >> 5) * 64, n0 = (i & 31) * 128;
            wait_cnt(SC_X + (m0 >> 6), 1);
            wait_cnt(SC_WF + (n0 >> 7), 8);
            wait_done();
            gemm_body<true, true, 64, 2>(g_xh, g_wfc, g_h, D_DIM, H_DIM, m0, n0);
            signal_cnt(SC_H + (m0 >> 6), 1);
        }
    } else {                                 // GEMM2 tiles
        const int i = bx - G2_BASE;
        if (i < G2_BIG_TILES) {
            const int m0 = (i >> 3) * 128, n0 = (i & 7) * 128;
            wait_cnt(SC_H + (m0 >> 6), 32);
            wait_cnt(SC_H + (m0 >> 6) + 1, 32);
            wait_cnt(SC_WP + (n0 >> 7), 32);
            wait_done();
            gemm_body<false, false, 128, 4>(g_h, g_wpr, out, H_DIM, D_DIM, m0, n0);
        } else {
            const int j = i - G2_BIG_TILES;
            const int m0 = G2_SMALL_ROW0 + (j >> 3) * 64, n0 = (j & 7) * 128;
            wait_cnt(SC_H + (m0 >> 6), 32);
            wait_cnt(SC_WP + (n0 >> 7), 32);
            wait_done();
            gemm_body<false, false, 64, 2>(g_h, g_wpr, out, H_DIM, D_DIM, m0, n0);
        }
    }
}

// counter reset (must strictly precede fused_all on the stream)
__global__ void reset_sync_kernel()
{
    if (threadIdx.x < 296) g_sync[threadIdx.x] = 0;
}

// ---------------- host side ----------------
extern "C" void kernel_launch(void* const* d_in, const int* in_sizes, int n_in,
                              void* d_out, int out_size)
{
    const float* x   = (const float*)d_in[0];  // [8192, 1024]
    const float* wfc = (const float*)d_in[1];  // [4096, 1024]
    const float* wpr = (const float*)d_in[2];  // [1024, 4096]
    float* out = (float*)d_out;                // [8192, 1024]

    cudaFuncSetAttribute(fused_all,
                         cudaFuncAttributeMaxDynamicSharedMemorySize, SMEM_TOTAL);

    reset_sync_kernel<<<1, 296>>>();

    // one launch: fp32->fp16 conversion CTAs + GEMM1 + GEMM2, all dependency-tracked
    fused_all<<<GRID_TOTAL, 256, SMEM_TOTAL>>>(
        (const float4*)x, (const float4*)wfc, (const float4*)wpr, out);
}

// round 16
// speedup vs baseline: 1.0211x; 1.0211x over previous
#include <cuda_runtime.h>
#include <cuda_fp16.h>
#include <cstdint>

// ---------------- problem dims ----------------
#define T_DIM 8192
#define D_DIM 1024
#define H_DIM 4096

// scratch (device globals: no allocation allowed)
__device__ __half g_h  [(size_t)T_DIM * H_DIM];   // 64 MB intermediate (fp16)
__device__ __half g_xh [(size_t)T_DIM * D_DIM];   // fp16 x
__device__ __half g_wfc[(size_t)H_DIM * D_DIM];   // fp16 W_fc
__device__ __half g_wpr[(size_t)D_DIM * H_DIM];   // fp16 W_proj
// sync counters: [0,8) wpr 128-row bands; [8,136) h 64-row bands
__device__ int    g_sync[136];

static constexpr int SC_WP = 0, SC_H = 8;

// ---------------- helpers ----------------
__device__ __forceinline__ uint32_t smem_u32(const void* p) {
    uint32_t a;
    asm("{ .reg .u64 t; cvta.to.shared.u64 t, %1; cvt.u32.u64 %0, t; }" : "=r"(a) : "l"(p));
    return a;
}
__device__ __forceinline__ uint32_t swz(uint32_t b) {   // SW128: XOR bits[6:4] with bits[9:7]
    return b ^ ((b >> 3) & 0x70u);
}
__device__ __forceinline__ void cp_async16(uint32_t saddr, const void* g) {
    asm volatile("cp.async.cg.shared.global [%0], [%1], 16;" :: "r"(saddr), "l"(g));
}
#define CP_COMMIT() asm volatile("cp.async.commit_group;" ::: "memory")
#define CP_WAIT1()  asm volatile("cp.async.wait_group 1;" ::: "memory")

#define LDSM_X4(r0, r1, r2, r3, addr) \
    asm volatile("ldmatrix.sync.aligned.m8n8.x4.shared.b16 {%0,%1,%2,%3}, [%4];" \
        : "=r"(r0), "=r"(r1), "=r"(r2), "=r"(r3) : "r"(addr))

// fp16 MMA, fp32 accumulate: D(16x8) += A(16x16) * B(16x8)
#define MMA_F16(c0, c1, c2, c3, a0, a1, a2, a3, b0, b1) \
    asm volatile("mma.sync.aligned.m16n8k16.row.col.f32.f16.f16.f32 " \
        "{%0,%1,%2,%3}, {%4,%5,%6,%7}, {%8,%9}, {%0,%1,%2,%3};" \
        : "+f"(c0), "+f"(c1), "+f"(c2), "+f"(c3) \
        : "r"(a0), "r"(a1), "r"(a2), "r"(a3), "r"(b0), "r"(b1))

// ---------------- GEMM config ----------------
static constexpr int BLK_N = 128;
static constexpr int BLK_K = 64;                 // fp16 elems -> 128 bytes per row
static constexpr int STAGES = 3;                 // <=96KB -> 2 CTAs / SM
static constexpr int B_BYTES = BLK_N * BLK_K * 2;          // 16384
static constexpr int SMEM_TOTAL = STAGES * (128 * 128 + B_BYTES);   // 98304 (TM=128 worst case)

// fused grid layout: G1 tiles, then wpr-conv CTAs, then G2 tiles
static constexpr int G1_BIG_TILES = 1760;        // rows 0-7039, 55x32
static constexpr int G1_SMALL_ROW0 = 7040;
static constexpr int G1_TOTAL = 2336;
static constexpr int WPCV_BASE = G1_TOTAL;       // 256 conv CTAs (32 per 128-row wpr band)
static constexpr int G2_BASE = WPCV_BASE + 256;  // 2592
static constexpr int G2_BIG_TILES = 296;         // rows 0-4735
static constexpr int G2_SMALL_ROW0 = 4736;
static constexpr int G2_TOTAL = 728;
static constexpr int GRID_TOTAL = G2_BASE + G2_TOTAL;   // 3320

// load one TMx64 A tile + 128x64 B tile (fp16) into stage at sBase
template <int TM>
__device__ __forceinline__ void load_tile_t(uint32_t sBase, const __half* __restrict__ gA,
                                            const __half* __restrict__ gB, int K, int kt, int tid)
{
    const int k0 = kt * BLK_K;
    constexpr int A_BY = TM * 128;
    #pragma unroll
    for (int i = 0; i < TM * 8 / 256; ++i) {       // A: TM*8 x 16B chunks / 256 thr
        int chunk = tid + i * 256;
        int row = chunk >> 3, unit = chunk & 7;    // 8 x 16B units per 128B row
        uint32_t off = row * 128 + unit * 16;
        cp_async16(sBase + swz(off), gA + (size_t)row * K + k0 + unit * 8);
    }
    #pragma unroll
    for (int i = 0; i < 4; ++i) {                  // B
        int chunk = tid + i * 256;
        int row = chunk >> 3, unit = chunk & 7;
        uint32_t off = row * 128 + unit * 16;
        cp_async16(sBase + A_BY + swz(off), gB + (size_t)row * K + k0 + unit * 8);
    }
}

// common mainloop body
template <bool RELU2, bool OUT16, int TM, int WGM>
__device__ __forceinline__ void gemm_body(
    const __half* __restrict__ A, const __half* __restrict__ B, void* __restrict__ Cv,
    int K, int ldc, int m0, int n0)
{
    extern __shared__ char smem[];
    constexpr int MI = TM / (16 * WGM);
    constexpr int NJ = WGM;
    constexpr int A_BY = TM * 128;
    constexpr int STG = A_BY + B_BYTES;
    const uint32_t sb = smem_u32(smem);
    const int tid  = threadIdx.x;
    const int lane = tid & 31;
    const int warp = tid >> 5;
    const int wm = (warp % WGM) * (TM / WGM);
    const int wn = (warp / WGM) * (16 * WGM);

    const __half* gA = A + (size_t)m0 * K;
    const __half* gB = B + (size_t)n0 * K;
    const int KT = K / BLK_K;

    // prologue: 2 stages in flight
    load_tile_t<TM>(sb, gA, gB, K, 0, tid);
    CP_COMMIT();
    load_tile_t<TM>(sb + STG, gA, gB, K, 1, tid);
    CP_COMMIT();

    // ldmatrix linear offsets (swizzle XOR applied per access)
    const uint32_t xmask = (uint32_t)(lane & 7) << 4;
    uint32_t aLin[MI];
    #pragma unroll
    for (int mi = 0; mi < MI; ++mi)
        aLin[mi] = (uint32_t)(wm + mi * 16 + (lane & 15)) * 128 + (uint32_t)(lane >> 4) * 16;
    uint32_t bLin[NJ];
    #pragma unroll
    for (int jp = 0; jp < NJ; ++jp)
        bLin[jp] = (uint32_t)(wn + jp * 16 + (lane & 15)) * 128 + (uint32_t)(lane >> 4) * 16;

    float c[MI][2 * NJ][4];
    #pragma unroll
    for (int mi = 0; mi < MI; ++mi)
        #pragma unroll
        for (int j = 0; j < 2 * NJ; ++j)
            #pragma unroll
            for (int q = 0; q < 4; ++q) c[mi][j][q] = 0.0f;

    int curSt = 0, pfSt = 2;
    for (int kt = 0; kt < KT; ++kt) {
        CP_WAIT1();
        __syncthreads();

        // prefetch k-tile kt+2 into the slot consumed at kt-1
        int nk = kt + 2;
        if (nk < KT) load_tile_t<TM>(sb + pfSt * STG, gA, gB, K, nk, tid);
        CP_COMMIT();
        if (++pfSt == STAGES) pfSt = 0;

        const uint32_t st = sb + curSt * STG;
        if (++curSt == STAGES) curSt = 0;

        #pragma unroll
        for (int s = 0; s < 4; ++s) {              // 4 x K=16 steps (32B each)
            const uint32_t add = s * 32;
            uint32_t a[MI][4], b[NJ][4];
            #pragma unroll
            for (int mi = 0; mi < MI; ++mi)
                LDSM_X4(a[mi][0], a[mi][1], a[mi][2], a[mi][3], st + ((aLin[mi] + add) ^ xmask));
            #pragma unroll
            for (int jp = 0; jp < NJ; ++jp)
                LDSM_X4(b[jp][0], b[jp][1], b[jp][2], b[jp][3],
                        st + A_BY + ((bLin[jp] + add) ^ xmask));
            #pragma unroll
            for (int mi = 0; mi < MI; ++mi)
                #pragma unroll
                for (int jp = 0; jp < NJ; ++jp) {
                    MMA_F16(c[mi][2 * jp][0], c[mi][2 * jp][1], c[mi][2 * jp][2], c[mi][2 * jp][3],
                            a[mi][0], a[mi][1], a[mi][2], a[mi][3], b[jp][0], b[jp][2]);
                    MMA_F16(c[mi][2 * jp + 1][0], c[mi][2 * jp + 1][1], c[mi][2 * jp + 1][2], c[mi][2 * jp + 1][3],
                            a[mi][0], a[mi][1], a[mi][2], a[mi][3], b[jp][1], b[jp][3]);
                }
        }
    }

    // epilogue
    const int row0 = m0 + wm + (lane >> 2);
    const int col0 = n0 + wn + (lane & 3) * 2;
    #pragma unroll
    for (int mi = 0; mi < MI; ++mi)
        #pragma unroll
        for (int rr = 0; rr < 2; ++rr) {
            const int row = row0 + mi * 16 + rr * 8;
            #pragma unroll
            for (int j = 0; j < 2 * NJ; ++j) {
                float v0 = c[mi][j][rr * 2], v1 = c[mi][j][rr * 2 + 1];
                if (RELU2) {
                    v0 = fmaxf(v0, 0.0f); v0 *= v0;
                    v1 = fmaxf(v1, 0.0f); v1 *= v1;
                }
                if (OUT16) {
                    __half* base = (__half*)Cv + (size_t)row * ldc + col0;
                    __half2 hv = __floats2half2_rn(v0, v1);
                    *reinterpret_cast<__half2*>(base + j * 8) = hv;
                } else {
                    float* base = (float*)Cv + (size_t)row * ldc + col0;
                    *reinterpret_cast<float2*>(base + j * 8) = make_float2(v0, v1);
                }
            }
        }
}

// signal: all threads fence+sync, one thread bumps counter(s)
__device__ __forceinline__ void signal_cnt(int idx0, int n)
{
    __threadfence();
    __syncthreads();
    if (threadIdx.x == 0) {
        atomicAdd(&g_sync[idx0], 1);
        if (n == 2) atomicAdd(&g_sync[idx0 + 1], 1);
    }
}

// wait: thread 0 spins until counter reaches target
__device__ __forceinline__ void wait_cnt(int idx, int target)
{
    if (threadIdx.x == 0)
        while (atomicAdd(&g_sync[idx], 0) < target) { __nanosleep(128); }
}
__device__ __forceinline__ void wait_done()
{
    if (threadIdx.x == 0) __threadfence();
    __syncthreads();
}

// fused: GEMM1 tiles, then wpr-conversion CTAs, then GEMM2 tiles
__global__ void __launch_bounds__(256, 2) gemm12_fused(
    const __half* __restrict__ xh, const __half* __restrict__ wfc,
    __half* __restrict__ h, const float4* __restrict__ wp_f32,
    __half* __restrict__ wprh, float* __restrict__ out)
{
    const int bx = blockIdx.x;
    if (bx < G1_TOTAL) {                     // GEMM1 tiles (inputs ready via pre-pass)
        if (bx < G1_BIG_TILES) {
            const int m0 = (bx >> 5) * 128;
            gemm_body<true, true, 128, 4>(xh, wfc, h, D_DIM, H_DIM, m0, (bx & 31) * 128);
            signal_cnt(SC_H + (m0 >> 6), 2);
        } else {
            const int i = bx - G1_BIG_TILES;
            const int m0 = G1_SMALL_ROW0 + (i >> 5) * 64;
            gemm_body<true, true, 64, 2>(xh, wfc, h, D_DIM, H_DIM, m0, (i & 31) * 128);
            signal_cnt(SC_H + (m0 >> 6), 1);
        }
    } else if (bx < G2_BASE) {               // wpr conversion: 32 CTAs per 128-row band
        const int off = bx - WPCV_BASE;      // 0..255; each converts 4096 float4
        const size_t b4 = (size_t)off * 4096;
        __half2* dst = (__half2*)wprh + b4 * 2;
        for (int i = threadIdx.x; i < 4096; i += 256) {
            float4 v = wp_f32[b4 + i];
            dst[2 * i]     = __floats2half2_rn(v.x, v.y);
            dst[2 * i + 1] = __floats2half2_rn(v.z, v.w);
        }
        signal_cnt(SC_WP + (off >> 5), 1);
    } else {                                 // GEMM2 tiles
        const int i = bx - G2_BASE;
        if (i < G2_BIG_TILES) {
            const int m0 = (i >> 3) * 128, n0 = (i & 7) * 128;
            wait_cnt(SC_H + (m0 >> 6), 32);
            wait_cnt(SC_H + (m0 >> 6) + 1, 32);
            wait_cnt(SC_WP + (n0 >> 7), 32);
            wait_done();
            gemm_body<false, false, 128, 4>(h, wprh, out, H_DIM, D_DIM, m0, n0);
        } else {
            const int j = i - G2_BIG_TILES;
            const int m0 = G2_SMALL_ROW0 + (j >> 3) * 64, n0 = (j & 7) * 128;
            wait_cnt(SC_H + (m0 >> 6), 32);
            wait_cnt(SC_WP + (n0 >> 7), 32);
            wait_done();
            gemm_body<false, false, 64, 2>(h, wprh, out, H_DIM, D_DIM, m0, n0);
        }
    }
}

// ---------------- pre-pass: convert x + wfc only (GEMM1's inputs) + counter reset ----------------
// blocks [0,1184): x (2M float4); [1184,1776): wfc (1M float4)
__global__ void to_half_xw_kernel(const float4* __restrict__ x,  __half2* __restrict__ xo,
                                  const float4* __restrict__ wf, __half2* __restrict__ wfo)
{
    if (blockIdx.x == 0 && threadIdx.x < 136) g_sync[threadIdx.x] = 0;  // reset counters
    const float4* src; __half2* dst; int n4, b0, nb;
    if (blockIdx.x < 1184) { src = x;  dst = xo;  n4 = T_DIM * D_DIM / 4; b0 = 0;    nb = 1184; }
    else                   { src = wf; dst = wfo; n4 = H_DIM * D_DIM / 4; b0 = 1184; nb = 592; }
    const int stride = nb * 256;
    #pragma unroll 2
    for (int i = (blockIdx.x - b0) * 256 + threadIdx.x; i < n4; i += stride) {
        float4 v = src[i];
        dst[2 * i]     = __floats2half2_rn(v.x, v.y);
        dst[2 * i + 1] = __floats2half2_rn(v.z, v.w);
    }
}

// ---------------- host side ----------------
extern "C" void kernel_launch(void* const* d_in, const int* in_sizes, int n_in,
                              void* d_out, int out_size)
{
    const float* x   = (const float*)d_in[0];  // [8192, 1024]
    const float* wfc = (const float*)d_in[1];  // [4096, 1024]
    const float* wpr = (const float*)d_in[2];  // [1024, 4096]
    float* out = (float*)d_out;                // [8192, 1024]

    __half *h, *xh, *wfch, *wprh;
    cudaGetSymbolAddress((void**)&h,    g_h);
    cudaGetSymbolAddress((void**)&xh,   g_xh);
    cudaGetSymbolAddress((void**)&wfch, g_wfc);
    cudaGetSymbolAddress((void**)&wprh, g_wpr);

    cudaFuncSetAttribute(gemm12_fused,
                         cudaFuncAttributeMaxDynamicSharedMemorySize, SMEM_TOTAL);

    // pre-pass: convert only x + wfc (GEMM1 inputs) at full occupancy; resets counters
    to_half_xw_kernel<<<1776, 256>>>((const float4*)x,   (__half2*)xh,
                                     (const float4*)wfc, (__half2*)wfch);

    // fused: GEMM1 + hidden wpr conversion + GEMM2 (band-dependency tracked)
    gemm12_fused<<<GRID_TOTAL, 256, SMEM_TOTAL>>>(
        xh, wfch, h, (const float4*)wpr, wprh, out);
}

// round 17
// speedup vs baseline: 1.0273x; 1.0061x over previous
#include <cuda_runtime.h>
#include <cuda_fp16.h>
#include <cstdint>

// ---------------- problem dims ----------------
#define T_DIM 8192
#define D_DIM 1024
#define H_DIM 4096

// scratch (device globals: no allocation allowed)
__device__ __half g_h  [(size_t)T_DIM * H_DIM];   // 64 MB intermediate (fp16)
__device__ __half g_xh [(size_t)T_DIM * D_DIM];   // fp16 x
__device__ __half g_wfc[(size_t)H_DIM * D_DIM];   // fp16 W_fc
__device__ __half g_wpr[(size_t)D_DIM * H_DIM];   // fp16 W_proj
// sync counters: [0,128) x 64-row bands (==4); [128,160) wfc 128-row bands (==8);
//                [160,168) wpr 128-row bands (==32); [168,296) h 64-row bands (==32)
__device__ int    g_sync[296];

static constexpr int SC_X = 0, SC_WF = 128, SC_WP = 160, SC_H = 168;

// ---------------- helpers ----------------
__device__ __forceinline__ uint32_t smem_u32(const void* p) {
    uint32_t a;
    asm("{ .reg .u64 t; cvta.to.shared.u64 t, %1; cvt.u32.u64 %0, t; }" : "=r"(a) : "l"(p));
    return a;
}
__device__ __forceinline__ uint32_t swz(uint32_t b) {   // SW128: XOR bits[6:4] with bits[9:7]
    return b ^ ((b >> 3) & 0x70u);
}
__device__ __forceinline__ void cp_async16(uint32_t saddr, const void* g) {
    asm volatile("cp.async.cg.shared.global [%0], [%1], 16;" :: "r"(saddr), "l"(g));
}
#define CP_COMMIT() asm volatile("cp.async.commit_group;" ::: "memory")
#define CP_WAIT1()  asm volatile("cp.async.wait_group 1;" ::: "memory")

#define LDSM_X4(r0, r1, r2, r3, addr) \
    asm volatile("ldmatrix.sync.aligned.m8n8.x4.shared.b16 {%0,%1,%2,%3}, [%4];" \
        : "=r"(r0), "=r"(r1), "=r"(r2), "=r"(r3) : "r"(addr))

// fp16 MMA, fp32 accumulate: D(16x8) += A(16x16) * B(16x8)
#define MMA_F16(c0, c1, c2, c3, a0, a1, a2, a3, b0, b1) \
    asm volatile("mma.sync.aligned.m16n8k16.row.col.f32.f16.f16.f32 " \
        "{%0,%1,%2,%3}, {%4,%5,%6,%7}, {%8,%9}, {%0,%1,%2,%3};" \
        : "+f"(c0), "+f"(c1), "+f"(c2), "+f"(c3) \
        : "r"(a0), "r"(a1), "r"(a2), "r"(a3), "r"(b0), "r"(b1))

// ---------------- GEMM config ----------------
static constexpr int BLK_N = 128;
static constexpr int BLK_K = 64;                 // fp16 elems -> 128 bytes per row
static constexpr int STAGES = 3;                 // <=96KB -> 2 CTAs / SM
static constexpr int B_BYTES = BLK_N * BLK_K * 2;          // 16384
static constexpr int SMEM_TOTAL = STAGES * (128 * 128 + B_BYTES);   // 98304 (TM=128 worst case)

// fused grid: G1 tiles then G2 tiles (conversion lives in the separate pre-pass kernel)
static constexpr int G1_BIG_TILES = 1760;        // rows 0-7039, 55x32
static constexpr int G1_SMALL_ROW0 = 7040;
static constexpr int G1_TOTAL = 2336;
static constexpr int G2_BIG_TILES = 296;         // rows 0-4735
static constexpr int G2_SMALL_ROW0 = 4736;
static constexpr int G2_TOTAL = 728;
static constexpr int GRID_TOTAL = G1_TOTAL + G2_TOTAL;   // 3064

// load one TMx64 A tile + 128x64 B tile (fp16) into stage at sBase
template <int TM>
__device__ __forceinline__ void load_tile_t(uint32_t sBase, const __half* __restrict__ gA,
                                            const __half* __restrict__ gB, int K, int kt, int tid)
{
    const int k0 = kt * BLK_K;
    constexpr int A_BY = TM * 128;
    #pragma unroll
    for (int i = 0; i < TM * 8 / 256; ++i) {       // A: TM*8 x 16B chunks / 256 thr
        int chunk = tid + i * 256;
        int row = chunk >> 3, unit = chunk & 7;    // 8 x 16B units per 128B row
        uint32_t off = row * 128 + unit * 16;
        cp_async16(sBase + swz(off), gA + (size_t)row * K + k0 + unit * 8);
    }
    #pragma unroll
    for (int i = 0; i < 4; ++i) {                  // B
        int chunk = tid + i * 256;
        int row = chunk >> 3, unit = chunk & 7;
        uint32_t off = row * 128 + unit * 16;
        cp_async16(sBase + A_BY + swz(off), gB + (size_t)row * K + k0 + unit * 8);
    }
}

// common mainloop body
template <bool RELU2, bool OUT16, int TM, int WGM>
__device__ __forceinline__ void gemm_body(
    const __half* __restrict__ A, const __half* __restrict__ B, void* __restrict__ Cv,
    int K, int ldc, int m0, int n0)
{
    extern __shared__ char smem[];
    constexpr int MI = TM / (16 * WGM);
    constexpr int NJ = WGM;
    constexpr int A_BY = TM * 128;
    constexpr int STG = A_BY + B_BYTES;
    const uint32_t sb = smem_u32(smem);
    const int tid  = threadIdx.x;
    const int lane = tid & 31;
    const int warp = tid >> 5;
    const int wm = (warp % WGM) * (TM / WGM);
    const int wn = (warp / WGM) * (16 * WGM);

    const __half* gA = A + (size_t)m0 * K;
    const __half* gB = B + (size_t)n0 * K;
    const int KT = K / BLK_K;

    // prologue: 2 stages in flight
    load_tile_t<TM>(sb, gA, gB, K, 0, tid);
    CP_COMMIT();
    load_tile_t<TM>(sb + STG, gA, gB, K, 1, tid);
    CP_COMMIT();

    // ldmatrix linear offsets (swizzle XOR applied per access)
    const uint32_t xmask = (uint32_t)(lane & 7) << 4;
    uint32_t aLin[MI];
    #pragma unroll
    for (int mi = 0; mi < MI; ++mi)
        aLin[mi] = (uint32_t)(wm + mi * 16 + (lane & 15)) * 128 + (uint32_t)(lane >> 4) * 16;
    uint32_t bLin[NJ];
    #pragma unroll
    for (int jp = 0; jp < NJ; ++jp)
        bLin[jp] = (uint32_t)(wn + jp * 16 + (lane & 15)) * 128 + (uint32_t)(lane >> 4) * 16;

    float c[MI][2 * NJ][4];
    #pragma unroll
    for (int mi = 0; mi < MI; ++mi)
        #pragma unroll
        for (int j = 0; j < 2 * NJ; ++j)
            #pragma unroll
            for (int q = 0; q < 4; ++q) c[mi][j][q] = 0.0f;

    int curSt = 0, pfSt = 2;
    for (int kt = 0; kt < KT; ++kt) {
        CP_WAIT1();
        __syncthreads();

        // prefetch k-tile kt+2 into the slot consumed at kt-1
        int nk = kt + 2;
        if (nk < KT) load_tile_t<TM>(sb + pfSt * STG, gA, gB, K, nk, tid);
        CP_COMMIT();
        if (++pfSt == STAGES) pfSt = 0;

        const uint32_t st = sb + curSt * STG;
        if (++curSt == STAGES) curSt = 0;

        #pragma unroll
        for (int s = 0; s < 4; ++s) {              // 4 x K=16 steps (32B each)
            const uint32_t add = s * 32;
            uint32_t a[MI][4], b[NJ][4];
            #pragma unroll
            for (int mi = 0; mi < MI; ++mi)
                LDSM_X4(a[mi][0], a[mi][1], a[mi][2], a[mi][3], st + ((aLin[mi] + add) ^ xmask));
            #pragma unroll
            for (int jp = 0; jp < NJ; ++jp)
                LDSM_X4(b[jp][0], b[jp][1], b[jp][2], b[jp][3],
                        st + A_BY + ((bLin[jp] + add) ^ xmask));
            #pragma unroll
            for (int mi = 0; mi < MI; ++mi)
                #pragma unroll
                for (int jp = 0; jp < NJ; ++jp) {
                    MMA_F16(c[mi][2 * jp][0], c[mi][2 * jp][1], c[mi][2 * jp][2], c[mi][2 * jp][3],
                            a[mi][0], a[mi][1], a[mi][2], a[mi][3], b[jp][0], b[jp][2]);
                    MMA_F16(c[mi][2 * jp + 1][0], c[mi][2 * jp + 1][1], c[mi][2 * jp + 1][2], c[mi][2 * jp + 1][3],
                            a[mi][0], a[mi][1], a[mi][2], a[mi][3], b[jp][1], b[jp][3]);
                }
        }
    }

    // epilogue
    const int row0 = m0 + wm + (lane >> 2);
    const int col0 = n0 + wn + (lane & 3) * 2;
    #pragma unroll
    for (int mi = 0; mi < MI; ++mi)
        #pragma unroll
        for (int rr = 0; rr < 2; ++rr) {
            const int row = row0 + mi * 16 + rr * 8;
            #pragma unroll
            for (int j = 0; j < 2 * NJ; ++j) {
                float v0 = c[mi][j][rr * 2], v1 = c[mi][j][rr * 2 + 1];
                if (RELU2) {
                    v0 = fmaxf(v0, 0.0f); v0 *= v0;
                    v1 = fmaxf(v1, 0.0f); v1 *= v1;
                }
                if (OUT16) {
                    __half* base = (__half*)Cv + (size_t)row * ldc + col0;
                    __half2 hv = __floats2half2_rn(v0, v1);
                    *reinterpret_cast<__half2*>(base + j * 8) = hv;
                } else {
                    float* base = (float*)Cv + (size_t)row * ldc + col0;
                    *reinterpret_cast<float2*>(base + j * 8) = make_float2(v0, v1);
                }
            }
        }
}

// signal: all threads fence+sync, one thread bumps counter(s)
__device__ __forceinline__ void signal_cnt(int idx0, int n)
{
    __threadfence();
    __syncthreads();
    if (threadIdx.x == 0) {
        atomicAdd(&g_sync[idx0], 1);
        if (n == 2) atomicAdd(&g_sync[idx0 + 1], 1);
    }
}

// wait: thread 0 spins until counter reaches target
__device__ __forceinline__ void wait_cnt(int idx, int target)
{
    if (threadIdx.x == 0)
        while (atomicAdd(&g_sync[idx], 0) < target) { __nanosleep(128); }
}
__device__ __forceinline__ void wait_done()
{
    if (threadIdx.x == 0) __threadfence();
    __syncthreads();
}

// fused GEMM1 + GEMM2 (runs concurrently with the pre-pass via PDL; gates on counters)
__global__ void __launch_bounds__(256, 2) gemm12_fused(
    const __half* __restrict__ xh, const __half* __restrict__ wfc,
    __half* __restrict__ h, const __half* __restrict__ wprh,
    float* __restrict__ out)
{
    const int bx = blockIdx.x;
    if (bx < G1_TOTAL) {                     // GEMM1 tiles: gate on x + wfc conversion bands
        if (bx < G1_BIG_TILES) {
            const int m0 = (bx >> 5) * 128, n0 = (bx & 31) * 128;
            wait_cnt(SC_X + (m0 >> 6), 4);
            wait_cnt(SC_X + (m0 >> 6) + 1, 4);
            wait_cnt(SC_WF + (n0 >> 7), 8);
            wait_done();
            gemm_body<true, true, 128, 4>(xh, wfc, h, D_DIM, H_DIM, m0, n0);
            signal_cnt(SC_H + (m0 >> 6), 2);
        } else {
            const int i = bx - G1_BIG_TILES;
            const int m0 = G1_SMALL_ROW0 + (i >> 5) * 64, n0 = (i & 31) * 128;
            wait_cnt(SC_X + (m0 >> 6), 4);
            wait_cnt(SC_WF + (n0 >> 7), 8);
            wait_done();
            gemm_body<true, true, 64, 2>(xh, wfc, h, D_DIM, H_DIM, m0, n0);
            signal_cnt(SC_H + (m0 >> 6), 1);
        }
    } else {                                 // GEMM2 tiles: gate on h + wpr bands
        const int i = bx - G1_TOTAL;
        if (i < G2_BIG_TILES) {
            const int m0 = (i >> 3) * 128, n0 = (i & 7) * 128;
            wait_cnt(SC_H + (m0 >> 6), 32);
            wait_cnt(SC_H + (m0 >> 6) + 1, 32);
            wait_cnt(SC_WP + (n0 >> 7), 32);
            wait_done();
            gemm_body<false, false, 128, 4>(h, wprh, out, H_DIM, D_DIM, m0, n0);
        } else {
            const int j = i - G2_BIG_TILES;
            const int m0 = G2_SMALL_ROW0 + (j >> 3) * 64, n0 = (j & 7) * 128;
            wait_cnt(SC_H + (m0 >> 6), 32);
            wait_cnt(SC_WP + (n0 >> 7), 32);
            wait_done();
            gemm_body<false, false, 64, 2>(h, wprh, out, H_DIM, D_DIM, m0, n0);
        }
    }
}

// ---------------- pre-pass: convert all three tensors, per-band blocks + signaling ----------------
// 1024 blocks: [0,512) x (4 per 64-row band); [512,768) wfc (8 per 128-row band);
//              [768,1024) wpr (32 per 128-row band). Each block converts 4096 float4.
__global__ void to_half_bands_kernel(const float4* __restrict__ x,  __half2* __restrict__ xo,
                                     const float4* __restrict__ wf, __half2* __restrict__ wfo,
                                     const float4* __restrict__ wp, __half2* __restrict__ wpo)
{
    // release dependent (fused) kernel launch as soon as all CTAs have started
    asm volatile("griddepcontrol.launch_dependents;" ::: "memory");

    const float4* src; __half2* dst; int cidx;
    if (blockIdx.x < 512)      { src = x  + (size_t)blockIdx.x * 4096;
                                 dst = xo + (size_t)blockIdx.x * 8192;
                                 cidx = SC_X + (blockIdx.x >> 2); }
    else if (blockIdx.x < 768) { const int off = blockIdx.x - 512;
                                 src = wf  + (size_t)off * 4096;
                                 dst = wfo + (size_t)off * 8192;
                                 cidx = SC_WF + (off >> 3); }
    else                       { const int off = blockIdx.x - 768;
                                 src = wp  + (size_t)off * 4096;
                                 dst = wpo + (size_t)off * 8192;
                                 cidx = SC_WP + (off >> 5); }
    #pragma unroll 4
    for (int i = threadIdx.x; i < 4096; i += 256) {
        float4 v = src[i];
        dst[2 * i]     = __floats2half2_rn(v.x, v.y);
        dst[2 * i + 1] = __floats2half2_rn(v.z, v.w);
    }
    signal_cnt(cidx, 1);
}

// counter reset (strictly precedes pre-pass on the stream)
__global__ void reset_sync_kernel()
{
    if (threadIdx.x < 296) g_sync[threadIdx.x] = 0;
}

// ---------------- host side ----------------
extern "C" void kernel_launch(void* const* d_in, const int* in_sizes, int n_in,
                              void* d_out, int out_size)
{
    const float* x   = (const float*)d_in[0];  // [8192, 1024]
    const float* wfc = (const float*)d_in[1];  // [4096, 1024]
    const float* wpr = (const float*)d_in[2];  // [1024, 4096]
    float* out = (float*)d_out;                // [8192, 1024]

    __half *h, *xh, *wfch, *wprh;
    cudaGetSymbolAddress((void**)&h,    g_h);
    cudaGetSymbolAddress((void**)&xh,   g_xh);
    cudaGetSymbolAddress((void**)&wfch, g_wfc);
    cudaGetSymbolAddress((void**)&wprh, g_wpr);

    cudaFuncSetAttribute(gemm12_fused,
                         cudaFuncAttributeMaxDynamicSharedMemorySize, SMEM_TOTAL);

    reset_sync_kernel<<<1, 296>>>();

    // pre-pass: per-band conversion of x/wfc/wpr at full occupancy; releases fused kernel early
    to_half_bands_kernel<<<1024, 256>>>((const float4*)x,   (__half2*)xh,
                                        (const float4*)wfc, (__half2*)wfch,
                                        (const float4*)wpr, (__half2*)wprh);

    // fused GEMM1+GEMM2, launched with programmatic stream serialization (PDL):
    // CTAs may begin placement while the pre-pass drains; counters gate data readiness.
    cudaLaunchConfig_t cfg = {};
    cfg.gridDim = dim3(GRID_TOTAL, 1, 1);
    cfg.blockDim = dim3(256, 1, 1);
    cfg.dynamicSmemBytes = SMEM_TOTAL;
    cfg.stream = 0;
    cudaLaunchAttribute at[1];
    at[0].id = cudaLaunchAttributeProgrammaticStreamSerialization;
    at[0].val.programmaticStreamSerializationAllowed = 1;
    cfg.attrs = at;
    cfg.numAttrs = 1;
    cudaError_t err = cudaLaunchKernelEx(&cfg, gemm12_fused,
                                         (const __half*)xh, (const __half*)wfch,
                                         h, (const __half*)wprh, out);
    if (err != cudaSuccess) {
        // fallback: plain serialized launch (R14 behavior)
        gemm12_fused<<<GRID_TOTAL, 256, SMEM_TOTAL>>>(xh, wfch, h, wprh, out);
    }
}